// round 16
// baseline (speedup 1.0000x reference)
#include <cuda_runtime.h>
#include <cstdint>

#define DENSE_L   1024
#define NUM_G     16
#define WIN       128                  // +-40 reach (validated: rel_err ~1.9e-7)
#define JBH       8                    // j-blocks per window half (2 halves = 16 blocks)
#define RB        8                    // rows per buffer
#define XS_STRIDE 1032                 // slot*1032 % 32 = slot*8 -> conflict-free phases
#define NTHREADS  512
#define NBUF      3
#define WG_ELEMS  (NUM_G * 512)        // 8192 floats

// W layout: idx = g*512 + jbh*256 + jb*32 + sub*8 + k*2 + par
//   l = base + jbh*64 + jb*8 + sub*2 + par ; k_global = g*4 + k
__device__ float g_Wt[WG_ELEMS];

typedef unsigned long long ull;

__device__ __forceinline__ int group_base(float w0, float w3) {
    float c = 0.5f * (w0 + w3);
    int bi = ((int)floorf(c) - 64) & ~3;
    bi = bi < 0 ? 0 : bi;
    bi = bi > (DENSE_L - WIN) ? (DENSE_L - WIN) : bi;
    return bi;
}

__global__ void precompute_kernel(const float* __restrict__ weight) {
    int idx = blockIdx.x * blockDim.x + threadIdx.x;
    if (idx >= WG_ELEMS) return;
    int par = idx & 1;
    int k   = (idx >> 1) & 3;
    int sub = (idx >> 3) & 3;
    int jb  = (idx >> 5) & 7;
    int jbh = (idx >> 8) & 1;
    int g   = idx >> 9;
    int base = group_base(weight[g * 4], weight[g * 4 + 3]);
    int l = base + jbh * 64 + jb * 8 + sub * 2 + par;
    float d = (float)(l + 1) - weight[g * 4 + k];
    g_Wt[idx] = expf(-d * d * 0.01f);
}

__device__ __forceinline__ void fma2(ull &a, ull xp, ull wp) {
    asm("fma.rn.f32x2 %0, %1, %2, %0;" : "+l"(a) : "l"(xp), "l"(wp));
}
__device__ __forceinline__ void add2(ull &a, ull b) {
    asm("add.rn.f32x2 %0, %0, %1;" : "+l"(a) : "l"(b));
}
__device__ __forceinline__ ull pack2(float lo, float hi) {
    ull u; asm("mov.b64 %0, {%1, %2};" : "=l"(u) : "f"(lo), "f"(hi)); return u;
}

__device__ __forceinline__ void cp16(void* dst_smem, const void* src_gmem) {
    unsigned int d = (unsigned int)__cvta_generic_to_shared(dst_smem);
    asm volatile("cp.async.cg.shared.global [%0], [%1], 16;\n" :: "r"(d), "l"(src_gmem));
}
__device__ __forceinline__ void cp_commit() { asm volatile("cp.async.commit_group;\n"); }
__device__ __forceinline__ void cp_wait2()  { asm volatile("cp.async.wait_group 2;\n" ::: "memory"); }

__device__ __forceinline__ void stage_tile(float* xb, const float* __restrict__ xg, int tid) {
    #pragma unroll
    for (int i = 0; i < (RB * DENSE_L / 4) / NTHREADS; i++) {   // 4 iterations
        int idx = tid + i * NTHREADS;
        int r   = idx >> 8;          // 256 float4 per row
        int c4  = idx & 255;
        cp16(&xb[r * XS_STRIDE + (c4 << 2)], &xg[(size_t)idx << 2]);
    }
}

extern __shared__ float smem_dyn[];

__global__ __launch_bounds__(NTHREADS, 1)
void sampling_kernel(const float* __restrict__ x,
                     const float* __restrict__ weight,
                     float* __restrict__ out,
                     int ntiles) {
    int tid = threadIdx.x;
    float* bufs[NBUF] = { smem_dyn,
                          smem_dyn + RB * XS_STRIDE,
                          smem_dyn + 2 * RB * XS_STRIDE };

    int g    = tid >> 5;             // warp = k-group (owns 4 k)
    int lane = tid & 31;
    int slot = lane & 3;             // rows slot, slot+4
    int sub  = (lane >> 2) & 3;      // l-pair within 8-l block
    int jbh  = (lane >> 4) & 1;      // window half
    int base = group_base(weight[g * 4], weight[g * 4 + 3]);

    // ---- W slice in registers, loaded ONCE: 8 jb x 4 k = 32 ull ----
    ull wk0[JBH], wk1[JBH], wk2[JBH], wk3[JBH];
    const float* wb = g_Wt + g * 512 + jbh * 256 + sub * 8;
    #pragma unroll
    for (int jb = 0; jb < JBH; jb++) {
        float4 v0 = *(const float4*)(wb + jb * 32);
        float4 v1 = *(const float4*)(wb + jb * 32 + 4);
        wk0[jb] = pack2(v0.x, v0.y);
        wk1[jb] = pack2(v0.z, v0.w);
        wk2[jb] = pack2(v1.x, v1.y);
        wk3[jb] = pack2(v1.z, v1.w);
    }

    const int G = gridDim.x;
    int t = blockIdx.x;

    // 3-stage prologue: two fetches in flight
    stage_tile(bufs[0], x + (long long)t * RB * DENSE_L, tid);
    cp_commit();
    if (t + G < ntiles)
        stage_tile(bufs[1], x + (long long)(t + G) * RB * DENSE_L, tid);
    cp_commit();

    int s = 0;
    for (; t < ntiles; t += G) {
        long long t2 = (long long)t + 2LL * G;
        int s2 = s + 2; if (s2 >= NBUF) s2 -= NBUF;
        if (t2 < ntiles)
            stage_tile(bufs[s2], x + t2 * RB * DENSE_L, tid);
        cp_commit();
        cp_wait2();                  // tile t's group retired (in-order)
        __syncthreads();

        const float* xr = bufs[s] + slot * XS_STRIDE + base + jbh * 64 + sub * 2;

        ull a00 = 0, a01 = 0, a02 = 0, a03 = 0;   // row slot
        ull a10 = 0, a11 = 0, a12 = 0, a13 = 0;   // row slot+4
        #pragma unroll
        for (int jb = 0; jb < JBH; jb++) {
            ull x0 = *(const ull*)(xr + jb * 8);
            ull x1 = *(const ull*)(xr + 4 * XS_STRIDE + jb * 8);
            fma2(a00, x0, wk0[jb]);
            fma2(a01, x0, wk1[jb]);
            fma2(a02, x0, wk2[jb]);
            fma2(a03, x0, wk3[jb]);
            fma2(a10, x1, wk0[jb]);
            fma2(a11, x1, wk1[jb]);
            fma2(a12, x1, wk2[jb]);
            fma2(a13, x1, wk3[jb]);
        }

        // reduce over sub (xor 4, 8) and jbh (xor 16)
        #pragma unroll
        for (int m = 4; m <= 16; m <<= 1) {
            add2(a00, __shfl_xor_sync(0xffffffffu, a00, m));
            add2(a01, __shfl_xor_sync(0xffffffffu, a01, m));
            add2(a02, __shfl_xor_sync(0xffffffffu, a02, m));
            add2(a03, __shfl_xor_sync(0xffffffffu, a03, m));
            add2(a10, __shfl_xor_sync(0xffffffffu, a10, m));
            add2(a11, __shfl_xor_sync(0xffffffffu, a11, m));
            add2(a12, __shfl_xor_sync(0xffffffffu, a12, m));
            add2(a13, __shfl_xor_sync(0xffffffffu, a13, m));
        }

        if ((lane & 28) == 0) {      // sub==0 && jbh==0 -> lanes 0..3
            float2 f0 = *(float2*)&a00, f1 = *(float2*)&a01;
            float2 f2 = *(float2*)&a02, f3 = *(float2*)&a03;
            long long row = (long long)t * RB + slot;
            *(float4*)&out[row * 64 + g * 4] = make_float4(
                f0.x + f0.y, f1.x + f1.y, f2.x + f2.y, f3.x + f3.y);
            f0 = *(float2*)&a10; f1 = *(float2*)&a11;
            f2 = *(float2*)&a12; f3 = *(float2*)&a13;
            *(float4*)&out[(row + 4) * 64 + g * 4] = make_float4(
                f0.x + f0.y, f1.x + f1.y, f2.x + f2.y, f3.x + f3.y);
        }
        __syncthreads();             // buf[s] fully consumed before restage
        s++; if (s >= NBUF) s -= NBUF;
    }
}

extern "C" void kernel_launch(void* const* d_in, const int* in_sizes, int n_in,
                              void* d_out, int out_size) {
    const float* x      = (const float*)d_in[0];
    const float* weight = (const float*)d_in[1];
    float* out = (float*)d_out;
    int R = in_sizes[0] / DENSE_L;
    int ntiles = R / RB;                 // 16384

    size_t smem = (size_t)(NBUF * RB * XS_STRIDE) * sizeof(float);  // 99072 B
    cudaFuncSetAttribute((const void*)sampling_kernel,
                         cudaFuncAttributeMaxDynamicSharedMemorySize, (int)smem);

    int sms = 148;
    cudaDeviceGetAttribute(&sms, cudaDevAttrMultiProcessorCount, 0);

    precompute_kernel<<<(WG_ELEMS + 255) / 256, 256>>>(weight);
    sampling_kernel<<<sms, NTHREADS, smem>>>(x, weight, out, ntiles);
}